// round 10
// baseline (speedup 1.0000x reference)
#include <cuda_runtime.h>
#include <cuda_bf16.h>
#include <cstdint>

#define Dd 64
#define Rr 8
#define MAXN 100000
#define MAXE 3200000
#define NCHUNK 9                  // 8 relations + root

// ---------------- device scratch (no allocation allowed) -------------------
__device__ __align__(256) float    g_hs[MAXN * Dd];    // gather source (fp32)
__device__ __align__(256) float    g_h1[MAXN * Dd];    // layer-1 raw output
__device__ __align__(256) unsigned g_ahi[MAXN * 32];   // bf16x2 root-A hi
__device__ __align__(256) unsigned g_alo[MAXN * 32];   // bf16x2 root-A lo
__device__ __align__(256) unsigned g_bhi[NCHUNK * 64 * 32]; // [c][n][k-pair]
__device__ __align__(256) unsigned g_blo[NCHUNK * 64 * 32];
__device__ __align__(256) int      g_base[MAXN * Rr + 1];
__device__ __align__(256) int      g_cur[MAXN * Rr];
__device__ __align__(256) int      g_bsum[1024];
__device__ __align__(256) int      g_ssrc[MAXE];       // seg-sorted src ids

// ---------------- sort kernels (seg = r*N + dst) ----------------------------
__global__ void zeroi_kernel(int* __restrict__ p, int n) {
    int i = blockIdx.x * blockDim.x + threadIdx.x;
    int stride = gridDim.x * blockDim.x;
    for (; i < n; i += stride) p[i] = 0;
}
__global__ void hist_kernel(const int* __restrict__ ei,
                            const int* __restrict__ et, int n, int E_) {
    int stride = gridDim.x * blockDim.x;
    for (int e = blockIdx.x * blockDim.x + threadIdx.x; e < E_; e += stride)
        atomicAdd(&g_base[et[e] * n + ei[E_ + e]], 1);
}
__global__ void scan1_kernel(int S) {
    __shared__ int sh[256];
    int tid = threadIdx.x;
    int i0 = blockIdx.x * 1024 + tid * 4;
    int v[4], t = 0;
    #pragma unroll
    for (int j = 0; j < 4; ++j) {
        int idx = i0 + j;
        v[j] = (idx < S) ? g_base[idx] : 0;
        t += v[j];
    }
    sh[tid] = t;
    __syncthreads();
    for (int off = 1; off < 256; off <<= 1) {
        int x = (tid >= off) ? sh[tid - off] : 0;
        __syncthreads();
        sh[tid] += x;
        __syncthreads();
    }
    int run = sh[tid] - t;
    if (tid == 255) g_bsum[blockIdx.x] = sh[255];
    #pragma unroll
    for (int j = 0; j < 4; ++j) {
        int idx = i0 + j;
        if (idx < S) g_base[idx] = run;
        run += v[j];
    }
}
__global__ void scan2_kernel(int nb) {
    __shared__ int sh[256];
    int tid = threadIdx.x;
    int v[4], t = 0;
    #pragma unroll
    for (int j = 0; j < 4; ++j) {
        int idx = tid * 4 + j;
        v[j] = (idx < nb) ? g_bsum[idx] : 0;
        t += v[j];
    }
    sh[tid] = t;
    __syncthreads();
    for (int off = 1; off < 256; off <<= 1) {
        int x = (tid >= off) ? sh[tid - off] : 0;
        __syncthreads();
        sh[tid] += x;
        __syncthreads();
    }
    int run = sh[tid] - t;
    #pragma unroll
    for (int j = 0; j < 4; ++j) {
        int idx = tid * 4 + j;
        if (idx < nb) g_bsum[idx] = run;
        run += v[j];
    }
}
__global__ void scan3_kernel(int S, int E_) {
    int i = blockIdx.x * blockDim.x + threadIdx.x;
    if (i < S) {
        int b = g_base[i] + g_bsum[i >> 10];
        g_base[i] = b;
        g_cur[i]  = b;
    }
    if (i == 0) g_base[S] = E_;
}
__global__ void place_kernel(const int* __restrict__ ei,
                             const int* __restrict__ et, int n, int E_) {
    int stride = gridDim.x * blockDim.x;
    for (int e = blockIdx.x * blockDim.x + threadIdx.x; e < E_; e += stride) {
        int seg = et[e] * n + ei[E_ + e];
        int pos = atomicAdd(&g_cur[seg], 1);
        g_ssrc[pos] = ei[e];
    }
}

// ---------------- bf16 split helpers ---------------------------------------
__device__ __forceinline__ void split2(float a, float b, unsigned& hi, unsigned& lo) {
    __nv_bfloat16 ha = __float2bfloat16_rn(a), hb = __float2bfloat16_rn(b);
    float ra = a - __bfloat162float(ha), rb = b - __bfloat162float(hb);
    __nv_bfloat162 H = __nv_bfloat162(ha, hb);
    __nv_bfloat162 L = __nv_bfloat162(__float2bfloat16_rn(ra), __float2bfloat16_rn(rb));
    hi = *reinterpret_cast<unsigned*>(&H);
    lo = *reinterpret_cast<unsigned*>(&L);
}

// mode 0: row = emb[x[node]]; mode 1: row = relu(h[node]).
// Writes fp32 gather-source g_hs AND bf16 hi/lo (root-chunk A).
__global__ void splita_kernel(const float* __restrict__ src,
                              const int* __restrict__ x, int n, int mode) {
    int total = n * 32;
    int stride = gridDim.x * blockDim.x;
    for (int j = blockIdx.x * blockDim.x + threadIdx.x; j < total; j += stride) {
        int node = j >> 5, q = j & 31;
        size_t row = (mode == 0) ? (size_t)x[node] : (size_t)node;
        float2 v = ((const float2*)src)[row * 32 + q];
        if (mode == 1) { v.x = fmaxf(v.x, 0.f); v.y = fmaxf(v.y, 0.f); }
        ((float2*)g_hs)[j] = v;
        unsigned hi, lo;
        split2(v.x, v.y, hi, lo);
        g_ahi[j] = hi; g_alo[j] = lo;
    }
}

// B-split + transpose: [c][outcol][k] rows for ldmatrix row.col.
__global__ void splitb_kernel(const float* __restrict__ W,
                              const float* __restrict__ root) {
    int j = blockIdx.x * blockDim.x + threadIdx.x;
    if (j >= NCHUNK * 64 * 32) return;
    int q = j & 31, col = (j >> 5) & 63, c = j >> 11;
    const float* B = (c < 8) ? (W + c * 4096) : root;
    float a = B[(2 * q) * 64 + col];
    float b = B[(2 * q + 1) * 64 + col];
    unsigned hi, lo;
    split2(a, b, hi, lo);
    g_bhi[j] = hi; g_blo[j] = lo;
}

// ---------------- fused RGCN layer -----------------------------------------
// per 128-dst tile: for c in 0..7: A = seg-mean (gathered via sorted lists);
// c==8: A = root rows (pre-split). MMA accumulates all chunks into fp32 regs.
#define BPITCH   144
#define SB_CHUNK (64 * BPITCH)
#define SB_HALF  (NCHUNK * SB_CHUNK)   // 82944
#define SB_TOTAL (2 * SB_HALF)         // 165888
#define APITCH   144
#define SA_HI    SB_TOTAL
#define SA_LO    (SA_HI + 128 * APITCH)
#define SM_BIAS  (SA_LO + 128 * APITCH)
#define SM_TOTAL (SM_BIAS + 256)       // 203,264 B

#define MMA(c0,c1,c2,c3, a, b0, b1)                                            \
    asm volatile("mma.sync.aligned.m16n8k16.row.col.f32.bf16.bf16.f32 "        \
                 "{%0,%1,%2,%3}, {%4,%5,%6,%7}, {%8,%9}, {%0,%1,%2,%3};"       \
                 : "+f"(c0), "+f"(c1), "+f"(c2), "+f"(c3)                      \
                 : "r"((a)[0]), "r"((a)[1]), "r"((a)[2]), "r"((a)[3]),         \
                   "r"(b0), "r"(b1))
#define LDSM_X2(b0, b1, addr)                                                  \
    asm volatile("ldmatrix.sync.aligned.m8n8.x2.shared.b16 {%0,%1}, [%2];"     \
                 : "=r"(b0), "=r"(b1) : "r"(addr))
#define LDSM_X4(r, addr)                                                       \
    asm volatile("ldmatrix.sync.aligned.m8n8.x4.shared.b16 {%0,%1,%2,%3}, [%4];" \
                 : "=r"((r)[0]), "=r"((r)[1]), "=r"((r)[2]), "=r"((r)[3])      \
                 : "r"(addr))

__global__ __launch_bounds__(512, 1)
void fused_layer(const float* __restrict__ bias,
                 float* __restrict__ out, int n) {
    extern __shared__ char sm[];
    int tid = threadIdx.x;

    // stage B (hi+lo) + bias once per block
    for (int i = tid; i < NCHUNK * 64 * 32; i += 512) {
        int c = i >> 11, col = (i >> 5) & 63, q = i & 31;
        int off = c * SB_CHUNK + col * BPITCH + q * 4;
        *(unsigned*)(sm + off)           = g_bhi[i];
        *(unsigned*)(sm + SB_HALF + off) = g_blo[i];
    }
    if (tid < 64) ((float*)(sm + SM_BIAS))[tid] = bias[tid];
    __syncthreads();

    uint32_t smb;
    asm("{ .reg .u64 t; cvta.to.shared.u64 t, %1; cvt.u32.u64 %0, t; }"
        : "=r"(smb) : "l"(sm));

    int warp = tid >> 5, lane = tid & 31;
    int rows16   = (warp & 7) * 16;     // 16 dst rows per warp
    int colhalf  = warp >> 3;           // 0/1: 32-col half
    int qt       = lane & 3;
    int groupid  = lane >> 2;
    // ldmatrix-A per-lane offset: rows (lane&7)+8*((lane>>3)&1), k-half lane>>4
    uint32_t aoff = (uint32_t)(((lane & 7) + ((lane >> 3) & 1) * 8) * APITCH
                               + (lane >> 4) * 16 + rows16 * APITCH);
    // ldmatrix-B per-lane base
    uint32_t bbase = smb + (lane & 7) * BPITCH + ((lane >> 3) & 1) * 16;

    int gg   = tid >> 4;                // gather group 0..31
    int glan = tid & 15;                // 16 lanes, 4 floats each

    int ntiles = (n + 127) >> 7;
    for (int tile = blockIdx.x; tile < ntiles; tile += gridDim.x) {
        int n0 = tile << 7;
        float C[4][4];
        #pragma unroll
        for (int j = 0; j < 4; ++j)
            #pragma unroll
            for (int q = 0; q < 4; ++q) C[j][q] = 0.f;

        for (int c = 0; c < NCHUNK; ++c) {
            __syncthreads();   // prev chunk's MMA done reading A smem
            if (c < 8) {
                // gather phase: 32 groups x 4 rows
                for (int srow = gg; srow < 128; srow += 32) {
                    int dst = n0 + srow;
                    unsigned h0 = 0, h1v = 0, l0 = 0, l1v = 0;
                    if (dst < n) {
                        int seg = c * n + dst;
                        int s = g_base[seg], e = g_base[seg + 1];
                        float4 acc = make_float4(0.f, 0.f, 0.f, 0.f);
                        for (int i = s; i < e; ++i) {
                            float4 v = ((const float4*)g_hs)[(size_t)g_ssrc[i] * 16 + glan];
                            acc.x += v.x; acc.y += v.y; acc.z += v.z; acc.w += v.w;
                        }
                        if (e > s) {
                            float sc = 1.0f / (float)(e - s);
                            acc.x *= sc; acc.y *= sc; acc.z *= sc; acc.w *= sc;
                            split2(acc.x, acc.y, h0, l0);
                            split2(acc.z, acc.w, h1v, l1v);
                        }
                    }
                    uint32_t doff = (uint32_t)(srow * APITCH + glan * 8);
                    *(uint2*)(sm + SA_HI + doff) = make_uint2(h0, h1v);
                    *(uint2*)(sm + SA_LO + doff) = make_uint2(l0, l1v);
                }
            } else {
                // root chunk: copy pre-split rows
                for (int i = tid; i < 128 * 32; i += 512) {
                    int row = i >> 5, q = i & 31;
                    int dst = n0 + row;
                    unsigned vh = 0, vl = 0;
                    if (dst < n) {
                        vh = g_ahi[(size_t)dst * 32 + q];
                        vl = g_alo[(size_t)dst * 32 + q];
                    }
                    uint32_t doff = (uint32_t)(row * APITCH + q * 4);
                    *(unsigned*)(sm + SA_HI + doff) = vh;
                    *(unsigned*)(sm + SA_LO + doff) = vl;
                }
            }
            __syncthreads();

            // A fragments (hi & lo) for this chunk
            unsigned ah[4][4], al[4][4];
            #pragma unroll
            for (int s = 0; s < 4; ++s) {
                LDSM_X4(ah[s], smb + SA_HI + aoff + s * 32);
                LDSM_X4(al[s], smb + SA_LO + aoff + s * 32);
            }
            uint32_t cb = bbase + c * SB_CHUNK + colhalf * 32 * BPITCH;
            #pragma unroll
            for (int j = 0; j < 4; ++j) {
                uint32_t jb = cb + j * 8 * BPITCH;
                #pragma unroll
                for (int s = 0; s < 4; ++s) {
                    unsigned bh0, bh1, bl0, bl1;
                    LDSM_X2(bh0, bh1, jb + s * 32);
                    LDSM_X2(bl0, bl1, jb + s * 32 + SB_HALF);
                    MMA(C[j][0], C[j][1], C[j][2], C[j][3], ah[s], bh0, bh1);
                    MMA(C[j][0], C[j][1], C[j][2], C[j][3], ah[s], bl0, bl1);
                    MMA(C[j][0], C[j][1], C[j][2], C[j][3], al[s], bh0, bh1);
                }
            }
        }

        // epilogue: bias + store
        int row0 = n0 + rows16 + groupid;
        int row1 = row0 + 8;
        const float* bsm = (const float*)(sm + SM_BIAS);
        #pragma unroll
        for (int j = 0; j < 4; ++j) {
            int col = colhalf * 32 + j * 8 + qt * 2;
            float b0 = bsm[col], b1 = bsm[col + 1];
            if (row0 < n)
                *(float2*)(out + (size_t)row0 * Dd + col) =
                    make_float2(C[j][0] + b0, C[j][1] + b1);
            if (row1 < n)
                *(float2*)(out + (size_t)row1 * Dd + col) =
                    make_float2(C[j][2] + b0, C[j][3] + b1);
        }
    }
}

// ---------------------------------------------------------------------------
extern "C" void kernel_launch(void* const* d_in, const int* in_sizes, int n_in,
                              void* d_out, int out_size) {
    const int*   x    = (const int*)d_in[0];
    const int*   ei   = (const int*)d_in[1];
    const int*   et   = (const int*)d_in[2];
    const float* emb  = (const float*)d_in[3];
    const float* W1   = (const float*)d_in[4];
    const float* rt1  = (const float*)d_in[5];
    const float* b1   = (const float*)d_in[6];
    const float* W2   = (const float*)d_in[7];
    const float* rt2  = (const float*)d_in[8];
    const float* b2   = (const float*)d_in[9];
    float*       out  = (float*)d_out;

    int n  = in_sizes[0];
    int E_ = in_sizes[2];
    int S  = n * Rr;

    void *ph1, *pb;
    cudaGetSymbolAddress(&ph1, g_h1);
    cudaGetSymbolAddress(&pb,  g_base);
    float* h1   = (float*)ph1;
    int*   base = (int*)pb;

    cudaFuncSetAttribute(fused_layer, cudaFuncAttributeMaxDynamicSharedMemorySize,
                         SM_TOTAL);

    // ---- one-time edge segment sort ----
    int nscan = (S + 1023) / 1024;
    zeroi_kernel<<<1024, 256>>>(base, S + 1);
    hist_kernel<<<4096, 256>>>(ei, et, n, E_);
    scan1_kernel<<<nscan, 256>>>(S);
    scan2_kernel<<<1, 256>>>(nscan);
    scan3_kernel<<<(S + 255) / 256, 256>>>(S, E_);
    place_kernel<<<4096, 256>>>(ei, et, n, E_);

    // ---- layer 1 ----
    splitb_kernel<<<(NCHUNK * 64 * 32 + 255) / 256, 256>>>(W1, rt1);
    splita_kernel<<<2048, 256>>>(emb, x, n, 0);
    fused_layer<<<148, 512, SM_TOTAL>>>(b1, h1, n);

    // ---- layer 2 ----
    splitb_kernel<<<(NCHUNK * 64 * 32 + 255) / 256, 256>>>(W2, rt2);
    splita_kernel<<<2048, 256>>>(h1, nullptr, n, 1);
    fused_layer<<<148, 512, SM_TOTAL>>>(b2, out, n);
}